// round 2
// baseline (speedup 1.0000x reference)
#include <cuda_runtime.h>
#include <cstdint>

// DiffGatedTopK: x [N=16384, D=4096] fp32.
// k = int(D*0.15) = 614. out = x * topk_mask * (sigmoid(top1-top2)*3 + 1)

#define DCOLS 4096
#define KSEL  614
#define NTHREADS 256
#define GAIN_C 3.0f

// float -> order-preserving unsigned key
__device__ __forceinline__ unsigned f2k(unsigned u) {
    return u ^ ((unsigned)(((int)u) >> 31) | 0x80000000u);
}
// inverse
__device__ __forceinline__ float k2f(unsigned k) {
    unsigned b = (k & 0x80000000u) ? (k ^ 0x80000000u) : ~k;
    return __uint_as_float(b);
}

__device__ __forceinline__ void top2_upd(unsigned &m1, unsigned &m2, unsigned v) {
    if (v > m1) { m2 = m1; m1 = v; }
    else if (v > m2) { m2 = v; }
}

__device__ __forceinline__ int warp_incl_scan(int v, int lane) {
    #pragma unroll
    for (int o = 1; o < 32; o <<= 1) {
        int n = __shfl_up_sync(0xFFFFFFFFu, v, o);
        if (lane >= o) v += n;
    }
    return v;
}

__global__ void __launch_bounds__(NTHREADS, 8)
diff_gated_topk_kernel(const float* __restrict__ x, float* __restrict__ out) {
    const int tid  = threadIdx.x;
    const int lane = tid & 31;
    const int wid  = tid >> 5;

    const float4* __restrict__ xr =
        reinterpret_cast<const float4*>(x + (size_t)blockIdx.x * DCOLS);
    float4* __restrict__ orow =
        reinterpret_cast<float4*>(out + (size_t)blockIdx.x * DCOLS);

    __shared__ unsigned hist[256];
    __shared__ unsigned s_ctrl[3];   // [0]=prefix  [1]=remaining  [2]=eq_count
    __shared__ unsigned s_m[16];     // per-warp (m1,m2)
    __shared__ float    s_gain;
    __shared__ int      s_warp[8];   // block-scan scratch

    // ---- load 16 values/thread into registers, coalesced float4 ----
    uint4 kq[4];
    unsigned m1 = 0u, m2 = 0u;
    #pragma unroll
    for (int i = 0; i < 4; i++) {
        float4 v = xr[tid + i * NTHREADS];
        uint4 kk;
        kk.x = f2k(__float_as_uint(v.x));
        kk.y = f2k(__float_as_uint(v.y));
        kk.z = f2k(__float_as_uint(v.z));
        kk.w = f2k(__float_as_uint(v.w));
        top2_upd(m1, m2, kk.x); top2_upd(m1, m2, kk.y);
        top2_upd(m1, m2, kk.z); top2_upd(m1, m2, kk.w);
        kq[i] = kk;
    }

    // ---- block top-2 (multiset) reduction in key space ----
    #pragma unroll
    for (int off = 16; off; off >>= 1) {
        unsigned o1 = __shfl_down_sync(0xFFFFFFFFu, m1, off);
        unsigned o2 = __shfl_down_sync(0xFFFFFFFFu, m2, off);
        unsigned n1 = max(m1, o1);
        unsigned n2 = max(min(m1, o1), max(m2, o2));
        m1 = n1; m2 = n2;
    }
    if (lane == 0) { s_m[2 * wid] = m1; s_m[2 * wid + 1] = m2; }
    if (tid == 0) { s_ctrl[0] = 0u; s_ctrl[1] = (unsigned)KSEL; }
    __syncthreads();
    if (tid == 0) {
        unsigned a1 = s_m[0], a2 = s_m[1];
        #pragma unroll
        for (int w = 1; w < 8; w++) {
            unsigned b1 = s_m[2 * w], b2 = s_m[2 * w + 1];
            unsigned n1 = max(a1, b1);
            a2 = max(min(a1, b1), max(a2, b2));
            a1 = n1;
        }
        float v1 = k2f(a1), v2 = k2f(a2);
        float d  = v1 - v2;                 // >= 0
        s_gain = GAIN_C / (1.0f + expf(-d)) + 1.0f;
    }
    // NOTE: s_gain is consumed only after several more __syncthreads below.

    // ---- 4-pass 8-bit radix select for exact k-th largest key ----
    #pragma unroll
    for (int pass = 0; pass < 4; pass++) {
        const int shift = 24 - 8 * pass;
        // prefix/rem valid: previous pass (or init) ended with __syncthreads
        const unsigned pref = s_ctrl[0];
        const unsigned rem  = s_ctrl[1];
        const unsigned pmask = pass ? (0xFFFFFFFFu << (shift + 8)) : 0u;

        hist[tid] = 0u;
        __syncthreads();

        #pragma unroll
        for (int i = 0; i < 4; i++) {
            unsigned kk[4] = { kq[i].x, kq[i].y, kq[i].z, kq[i].w };
            #pragma unroll
            for (int j = 0; j < 4; j++) {
                unsigned key = kk[j];
                bool act = ((key & pmask) == pref);
                unsigned bin = (key >> shift) & 0xFFu;
                // warp-aggregated histogram: inactive lanes get unique dummies
                unsigned tag = act ? bin : (0x100u + (unsigned)lane);
                unsigned grp = __match_any_sync(0xFFFFFFFFu, tag);
                int leader = __ffs(grp) - 1;
                if (act && lane == leader)
                    atomicAdd(&hist[bin], (unsigned)__popc(grp));
            }
        }
        __syncthreads();

        // ---- parallel bin selection: suffix scan from bin 255 downward ----
        // thread tid owns bin b = 255 - tid; suffix_incl = sum_{b'>=b} hist[b']
        const int b = 255 - tid;
        int c = (int)hist[b];
        int incl = warp_incl_scan(c, lane);
        if (lane == 31) s_warp[wid] = incl;
        __syncthreads();
        if (wid == 0) {
            int w = (lane < 8) ? s_warp[lane] : 0;
            int wi = warp_incl_scan(w, lane);
            if (lane < 8) s_warp[lane] = wi;
        }
        __syncthreads();
        int suffix_incl = (wid ? s_warp[wid - 1] : 0) + incl;
        int suffix_excl = suffix_incl - c;      // count of keys strictly above bin b
        if (suffix_excl < (int)rem && (int)rem <= suffix_incl) {
            // unique thread: selected digit
            s_ctrl[0] = pref | ((unsigned)b << shift);
            s_ctrl[1] = rem - (unsigned)suffix_excl;   // needed from == bucket
            if (pass == 3) s_ctrl[2] = (unsigned)c;    // eq_count
        }
        __syncthreads();
    }

    const unsigned T      = s_ctrl[0];
    const unsigned needed = s_ctrl[1];
    const unsigned eqc    = s_ctrl[2];
    const float    gain   = s_gain;
    const bool use_rank   = (eqc != needed);   // rare: duplicated threshold value

    // ---- rare path: rank equal-to-threshold elements in exact column order ----
    // column(c) = i*1024 + tid*4 + j  -> order over (i, tid, j)
    int base[4] = {0, 0, 0, 0};
    if (use_rank) {
        int chunkbase = 0;
        #pragma unroll
        for (int i = 0; i < 4; i++) {
            unsigned kk[4] = { kq[i].x, kq[i].y, kq[i].z, kq[i].w };
            int c = (kk[0] == T) + (kk[1] == T) + (kk[2] == T) + (kk[3] == T);
            int incl = warp_incl_scan(c, lane);
            if (lane == 31) s_warp[wid] = incl;
            __syncthreads();
            if (wid == 0) {
                int w = (lane < 8) ? s_warp[lane] : 0;
                int wi = warp_incl_scan(w, lane);
                if (lane < 8) s_warp[lane] = wi;
            }
            __syncthreads();
            int offset = wid ? s_warp[wid - 1] : 0;
            base[i] = chunkbase + offset + incl - c;
            chunkbase += s_warp[7];
            __syncthreads();   // protect s_warp reuse
        }
    }

    // ---- write pass: reconstruct x from keys (no 2nd global read) ----
    #pragma unroll
    for (int i = 0; i < 4; i++) {
        unsigned kk[4] = { kq[i].x, kq[i].y, kq[i].z, kq[i].w };
        int r = base[i];
        float o[4];
        #pragma unroll
        for (int j = 0; j < 4; j++) {
            unsigned key = kk[j];
            bool inc;
            if (key > T) inc = true;
            else if (key == T) {
                if (!use_rank) inc = true;
                else { inc = (r < (int)needed); r++; }
            } else inc = false;
            o[j] = inc ? (k2f(key) * gain) : 0.0f;
        }
        float4 ov = make_float4(o[0], o[1], o[2], o[3]);
        orow[tid + i * NTHREADS] = ov;
    }
}

extern "C" void kernel_launch(void* const* d_in, const int* in_sizes, int n_in,
                              void* d_out, int out_size) {
    const float* x = (const float*)d_in[0];
    float* out = (float*)d_out;
    int nrows = in_sizes[0] / DCOLS;
    diff_gated_topk_kernel<<<nrows, NTHREADS>>>(x, out);
}

// round 3
// speedup vs baseline: 8.3909x; 8.3909x over previous
#include <cuda_runtime.h>
#include <cstdint>

// DiffGatedTopK: x [N=16384, D=4096] fp32.
// k = int(D*0.15) = 614. out = x * topk_mask * (sigmoid(top1-top2)*3 + 1)

#define DCOLS 4096
#define KSEL  614
#define NT    256
#define GAIN_C 3.0f

// float -> order-preserving unsigned key
__device__ __forceinline__ unsigned f2k(unsigned u) {
    return u ^ ((unsigned)(((int)u) >> 31) | 0x80000000u);
}
// inverse
__device__ __forceinline__ float k2f(unsigned k) {
    unsigned b = (k & 0x80000000u) ? (k ^ 0x80000000u) : ~k;
    return __uint_as_float(b);
}

__device__ __forceinline__ void top2_upd(unsigned &m1, unsigned &m2, unsigned v) {
    if (v > m1) { m2 = m1; m1 = v; }
    else if (v > m2) { m2 = v; }
}

__device__ __forceinline__ int warp_incl_scan(int v, int lane) {
    #pragma unroll
    for (int o = 1; o < 32; o <<= 1) {
        int n = __shfl_up_sync(0xFFFFFFFFu, v, o);
        if (lane >= o) v += n;
    }
    return v;
}

__global__ void __launch_bounds__(NT, 6)
diff_gated_topk_kernel(const float* __restrict__ x, float* __restrict__ out) {
    const int tid  = threadIdx.x;
    const int lane = tid & 31;
    const int wid  = tid >> 5;

    const float4* __restrict__ xr =
        reinterpret_cast<const float4*>(x + (size_t)blockIdx.x * DCOLS);
    float4* __restrict__ orow =
        reinterpret_cast<float4*>(out + (size_t)blockIdx.x * DCOLS);

    __shared__ int      s_cnt[2][8];   // double-buffered per-warp partials
    __shared__ unsigned s_m[16];       // per-warp (m1,m2) for top-2
    __shared__ float    s_gain;
    __shared__ int      s_warp[8];     // rare tie-rank scratch

    // ---- load 16 values/thread into registers, coalesced float4 ----
    uint4 kq[4];
    unsigned m1 = 0u, m2 = 0u;
    #pragma unroll
    for (int i = 0; i < 4; i++) {
        float4 v = xr[tid + i * NT];
        uint4 kk;
        kk.x = f2k(__float_as_uint(v.x));
        kk.y = f2k(__float_as_uint(v.y));
        kk.z = f2k(__float_as_uint(v.z));
        kk.w = f2k(__float_as_uint(v.w));
        top2_upd(m1, m2, kk.x); top2_upd(m1, m2, kk.y);
        top2_upd(m1, m2, kk.z); top2_upd(m1, m2, kk.w);
        kq[i] = kk;
    }

    // ---- block top-2 (multiset) -> gain (computed once by tid 0) ----
    #pragma unroll
    for (int off = 16; off; off >>= 1) {
        unsigned o1 = __shfl_down_sync(0xFFFFFFFFu, m1, off);
        unsigned o2 = __shfl_down_sync(0xFFFFFFFFu, m2, off);
        unsigned n1 = max(m1, o1);
        unsigned n2 = max(min(m1, o1), max(m2, o2));
        m1 = n1; m2 = n2;
    }
    if (lane == 0) { s_m[2 * wid] = m1; s_m[2 * wid + 1] = m2; }
    __syncthreads();
    if (tid == 0) {
        unsigned a1 = s_m[0], a2 = s_m[1];
        #pragma unroll
        for (int w = 1; w < 8; w++) {
            unsigned b1 = s_m[2 * w], b2 = s_m[2 * w + 1];
            unsigned n1 = max(a1, b1);
            a2 = max(min(a1, b1), max(a2, b2));
            a1 = n1;
        }
        float d = k2f(a1) - k2f(a2);        // >= 0
        s_gain = GAIN_C / (1.0f + expf(-d)) + 1.0f;
    }
    // s_gain consumed only after the (barrier-laden) bit loop below.

    // ---- bit-serial radix descent, atomic-free, 1 barrier/round ----
    unsigned pref = 0u;
    int rem = KSEL, active = DCOLS;
    unsigned T = 0u;
    int needed = 0, eqc = 0;
    int parity = 0;
    bool early = false;

    for (int shift = 31; shift >= 0; --shift) {
        const unsigned cand = (pref >> shift) | 1u;
        int cnt = 0;
        #pragma unroll
        for (int i = 0; i < 4; i++) {
            cnt += (kq[i].x >> shift) == cand;
            cnt += (kq[i].y >> shift) == cand;
            cnt += (kq[i].z >> shift) == cand;
            cnt += (kq[i].w >> shift) == cand;
        }
        cnt = __reduce_add_sync(0xFFFFFFFFu, cnt);     // REDUX.SUM
        if (lane == 0) s_cnt[parity][wid] = cnt;
        __syncthreads();
        // every warp redundantly forms the block sum (uniform state)
        int v = (lane < 8) ? s_cnt[parity][lane] : 0;
        v += __shfl_down_sync(0xFFFFFFFFu, v, 4);
        v += __shfl_down_sync(0xFFFFFFFFu, v, 2);
        v += __shfl_down_sync(0xFFFFFFFFu, v, 1);
        const int c1 = __shfl_sync(0xFFFFFFFFu, v, 0);
        parity ^= 1;

        if (c1 >= rem) { pref |= (1u << shift); active = c1; }
        else           { rem -= c1; active -= c1; }

        if (active == rem) {
            // all current candidates included: T = min over active keys,
            // inclusion predicate becomes key >= T (no tie-ranking needed)
            const unsigned hp = pref >> shift;
            unsigned mn = 0xFFFFFFFFu;
            #pragma unroll
            for (int i = 0; i < 4; i++) {
                if ((kq[i].x >> shift) == hp) mn = min(mn, kq[i].x);
                if ((kq[i].y >> shift) == hp) mn = min(mn, kq[i].y);
                if ((kq[i].z >> shift) == hp) mn = min(mn, kq[i].z);
                if ((kq[i].w >> shift) == hp) mn = min(mn, kq[i].w);
            }
            mn = __reduce_min_sync(0xFFFFFFFFu, mn);   // REDUX.UMIN
            if (lane == 0) s_cnt[parity][wid] = (int)mn;
            __syncthreads();
            unsigned m = (lane < 8) ? (unsigned)s_cnt[parity][lane] : 0xFFFFFFFFu;
            m = min(m, __shfl_down_sync(0xFFFFFFFFu, m, 4));
            m = min(m, __shfl_down_sync(0xFFFFFFFFu, m, 2));
            m = min(m, __shfl_down_sync(0xFFFFFFFFu, m, 1));
            T = __shfl_sync(0xFFFFFFFFu, m, 0);
            parity ^= 1;
            early = true;
            break;
        }
    }
    if (!early) {                 // duplicated threshold key (rare)
        T = pref; needed = rem; eqc = active;
    }
    const bool use_rank = (!early) && (eqc != needed);

    // ---- rare path: rank ==T elements in exact column order ----
    // column(c) = i*1024 + tid*4 + j  -> order over (i, tid, j)
    int base[4] = {0, 0, 0, 0};
    if (use_rank) {
        int chunkbase = 0;
        #pragma unroll
        for (int i = 0; i < 4; i++) {
            unsigned kk[4] = { kq[i].x, kq[i].y, kq[i].z, kq[i].w };
            int c = (kk[0] == T) + (kk[1] == T) + (kk[2] == T) + (kk[3] == T);
            int incl = warp_incl_scan(c, lane);
            if (lane == 31) s_warp[wid] = incl;
            __syncthreads();
            if (wid == 0) {
                int w = (lane < 8) ? s_warp[lane] : 0;
                int wi = warp_incl_scan(w, lane);
                if (lane < 8) s_warp[lane] = wi;
            }
            __syncthreads();
            int offset = wid ? s_warp[wid - 1] : 0;
            base[i] = chunkbase + offset + incl - c;
            chunkbase += s_warp[7];
            __syncthreads();
        }
    } else {
        __syncthreads();   // make s_gain visible (written by tid 0 pre-loop)
    }

    const float gain = s_gain;

    // ---- write pass: reconstruct x from keys (no 2nd global read) ----
    #pragma unroll
    for (int i = 0; i < 4; i++) {
        unsigned kk[4] = { kq[i].x, kq[i].y, kq[i].z, kq[i].w };
        int r = base[i];
        float o[4];
        #pragma unroll
        for (int j = 0; j < 4; j++) {
            unsigned key = kk[j];
            bool inc;
            if (!use_rank) {
                inc = (key >= T);
            } else {
                if (key > T) inc = true;
                else if (key == T) { inc = (r < needed); r++; }
                else inc = false;
            }
            o[j] = inc ? (k2f(key) * gain) : 0.0f;
        }
        orow[tid + i * NT] = make_float4(o[0], o[1], o[2], o[3]);
    }
}

extern "C" void kernel_launch(void* const* d_in, const int* in_sizes, int n_in,
                              void* d_out, int out_size) {
    const float* x = (const float*)d_in[0];
    float* out = (float*)d_out;
    int nrows = in_sizes[0] / DCOLS;
    diff_gated_topk_kernel<<<nrows, NT>>>(x, out);
}

// round 4
// speedup vs baseline: 14.5372x; 1.7325x over previous
#include <cuda_runtime.h>
#include <cstdint>
#include <float.h>

// DiffGatedTopK: x [N=16384, D=4096] fp32.
// k = int(D*0.15) = 614. out = x * topk_mask * (sigmoid(top1-top2)*3 + 1)

#define DCOLS 4096
#define KSEL  614
#define NT    256
#define GAIN_C 3.0f
#define CAP   128

// float <-> order-preserving unsigned key (for interval bookkeeping only)
__device__ __forceinline__ unsigned f2k_f(float f) {
    unsigned u = __float_as_uint(f);
    return u ^ ((unsigned)(((int)u) >> 31) | 0x80000000u);
}
__device__ __forceinline__ float k2f(unsigned k) {
    unsigned b = (k & 0x80000000u) ? (k ^ 0x80000000u) : ~k;
    return __uint_as_float(b);
}

__device__ __forceinline__ int warp_incl_scan(int v, int lane) {
    #pragma unroll
    for (int o = 1; o < 32; o <<= 1) {
        int n = __shfl_up_sync(0xFFFFFFFFu, v, o);
        if (lane >= o) v += n;
    }
    return v;
}

// count of the 16 register-resident values >= t
#define CNT16_GE(t, res) do {                                            \
    int _c = 0;                                                          \
    _c += (r0.x >= (t)) + (r0.y >= (t)) + (r0.z >= (t)) + (r0.w >= (t));\
    _c += (r1.x >= (t)) + (r1.y >= (t)) + (r1.z >= (t)) + (r1.w >= (t));\
    _c += (r2.x >= (t)) + (r2.y >= (t)) + (r2.z >= (t)) + (r2.w >= (t));\
    _c += (r3.x >= (t)) + (r3.y >= (t)) + (r3.z >= (t)) + (r3.w >= (t));\
    (res) = _c; } while (0)

__global__ void __launch_bounds__(NT, 6)
diff_gated_topk_kernel(const float* __restrict__ x, float* __restrict__ out) {
    const int tid  = threadIdx.x;
    const int lane = tid & 31;
    const int wid  = tid >> 5;

    const float4* __restrict__ xr =
        reinterpret_cast<const float4*>(x + (size_t)blockIdx.x * DCOLS);
    float4* __restrict__ orow =
        reinterpret_cast<float4*>(out + (size_t)blockIdx.x * DCOLS);

    __shared__ int   s_cnt[2][8];     // double-buffered per-warp count partials
    __shared__ float s_m[16];         // per-warp (m1,m2) for top-2
    __shared__ float s_gain;
    __shared__ int   s_warp[8];       // scan scratch (rare tie path)
    __shared__ float s_small[CAP];    // epilogue candidate buffer
    __shared__ int   s_n;
    __shared__ float s_T;
    __shared__ int   s_needed, s_eqc;

    // ---- load 16 values/thread, coalesced float4; track top-2 ----
    float4 r0, r1, r2, r3;
    float m1 = -FLT_MAX, m2 = -FLT_MAX;
    r0 = xr[tid];            r1 = xr[tid + NT];
    r2 = xr[tid + 2 * NT];   r3 = xr[tid + 3 * NT];
    #define T2(v) { float _v = (v); if (_v > m1) { m2 = m1; m1 = _v; } else if (_v > m2) m2 = _v; }
    T2(r0.x) T2(r0.y) T2(r0.z) T2(r0.w)
    T2(r1.x) T2(r1.y) T2(r1.z) T2(r1.w)
    T2(r2.x) T2(r2.y) T2(r2.z) T2(r2.w)
    T2(r3.x) T2(r3.y) T2(r3.z) T2(r3.w)
    #undef T2

    // ---- block top-2 (multiset) -> gain ----
    #pragma unroll
    for (int off = 16; off; off >>= 1) {
        float o1 = __shfl_down_sync(0xFFFFFFFFu, m1, off);
        float o2 = __shfl_down_sync(0xFFFFFFFFu, m2, off);
        float n1 = fmaxf(m1, o1);
        float n2 = fmaxf(fminf(m1, o1), fmaxf(m2, o2));
        m1 = n1; m2 = n2;
    }
    if (lane == 0) { s_m[2 * wid] = m1; s_m[2 * wid + 1] = m2; }
    if (tid == 0) s_n = 0;
    __syncthreads();
    if (tid == 0) {
        float a1 = s_m[0], a2 = s_m[1];
        #pragma unroll
        for (int w = 1; w < 8; w++) {
            float b1 = s_m[2 * w], b2 = s_m[2 * w + 1];
            float n1 = fmaxf(a1, b1);
            a2 = fmaxf(fminf(a1, b1), fmaxf(a2, b2));
            a1 = n1;
        }
        float d = a1 - a2;   // >= 0
        s_gain = GAIN_C / (1.0f + expf(-d)) + 1.0f;
    }

    // ---- bracket round: two probes counted in one pass (packed 16-bit) ----
    const float PA = 0.85f, PB = 1.30f;
    int cA, cB;
    CNT16_GE(PA, cA);
    CNT16_GE(PB, cB);
    {
        int pc = cA | (cB << 16);
        pc = __reduce_add_sync(0xFFFFFFFFu, pc);
        if (lane == 0) s_cnt[0][wid] = pc;
        __syncthreads();
        int v = (lane < 8) ? s_cnt[0][lane] : 0;
        v += __shfl_down_sync(0xFFFFFFFFu, v, 4);
        v += __shfl_down_sync(0xFFFFFFFFu, v, 2);
        v += __shfl_down_sync(0xFFFFFFFFu, v, 1);
        v = __shfl_sync(0xFFFFFFFFu, v, 0);
        cA = v & 0xFFFF; cB = v >> 16;
    }

    unsigned lo, hi; int clo, chi;
    if (cA >= KSEL && cB < KSEL)      { lo = f2k_f(PA); clo = cA;   hi = f2k_f(PB); chi = cB; }
    else if (cB >= KSEL)              { lo = f2k_f(PB); clo = cB;   hi = f2k_f(FLT_MAX); chi = 0; }
    else                              { lo = f2k_f(-FLT_MAX); clo = DCOLS; hi = f2k_f(PA); chi = cA; }

    // ---- interpolation / bisection descent ----
    int active = clo - chi;
    int parity = 1, round = 0;
    while (active > CAP && hi - lo > 1u && round < 64) {
        unsigned m;
        if (round & 1) {
            m = lo + ((hi - lo) >> 1);
        } else {
            float flo = k2f(lo), fhi = k2f(hi);
            float t = flo + (fhi - flo) * ((float)(clo - KSEL) / (float)(clo - chi));
            m = f2k_f(t);
            if (m <= lo || m >= hi) m = lo + ((hi - lo) >> 1);
        }
        float fm = k2f(m);
        int cm;
        CNT16_GE(fm, cm);
        cm = __reduce_add_sync(0xFFFFFFFFu, cm);
        if (lane == 0) s_cnt[parity][wid] = cm;
        __syncthreads();
        int v = (lane < 8) ? s_cnt[parity][lane] : 0;
        v += __shfl_down_sync(0xFFFFFFFFu, v, 4);
        v += __shfl_down_sync(0xFFFFFFFFu, v, 2);
        v += __shfl_down_sync(0xFFFFFFFFu, v, 1);
        cm = __shfl_sync(0xFFFFFFFFu, v, 0);
        parity ^= 1;
        if (cm >= KSEL) { lo = m; clo = cm; } else { hi = m; chi = cm; }
        active = clo - chi;
        round++;
    }

    float T; int needed, eqc;
    if (active <= CAP) {
        // ---- epilogue: compact candidates in [flo, fhi), rank exactly ----
        const float flo = k2f(lo), fhi = k2f(hi);
        __syncthreads();                 // s_n==0 visible; prior s_cnt reads done
        #define PUT(v) { float _v = (v); if (_v >= flo && _v < fhi) { \
                           int _p = atomicAdd(&s_n, 1); if (_p < CAP) s_small[_p] = _v; } }
        PUT(r0.x) PUT(r0.y) PUT(r0.z) PUT(r0.w)
        PUT(r1.x) PUT(r1.y) PUT(r1.z) PUT(r1.w)
        PUT(r2.x) PUT(r2.y) PUT(r2.z) PUT(r2.w)
        PUT(r3.x) PUT(r3.y) PUT(r3.z) PUT(r3.w)
        #undef PUT
        __syncthreads();
        int cnt = min(s_n, CAP);         // == active
        int k_small = KSEL - chi;        // 1 <= k_small <= cnt
        if (tid < cnt) {
            float v = s_small[tid];
            int cge = 0, cgt = 0;
            for (int j = 0; j < cnt; j++) {
                float w = s_small[j];
                cge += (w >= v);
                cgt += (w > v);
            }
            if (cgt < k_small && k_small <= cge) {   // v is the k_small-th largest
                s_T = v;
                s_needed = k_small - cgt;            // how many ==T to include
                s_eqc = cge - cgt;                   // total ==T in row
            }
        }
        __syncthreads();
        T = s_T; needed = s_needed; eqc = s_eqc;
    } else {
        // interval width 1: all active values equal k2f(lo)
        T = k2f(lo); needed = KSEL - chi; eqc = active;
        __syncthreads();                 // make s_gain safely visible (1+ barriers passed anyway)
    }

    const bool use_rank = (needed != eqc);   // rare: partial tie at threshold

    // ---- rare path: rank ==T elements in exact column order ----
    // column(c) = i*1024 + tid*4 + j  -> order over (i, tid, j)
    int base0 = 0, base1 = 0, base2 = 0, base3 = 0;
    if (use_rank) {
        int chunkbase = 0;
        float4 rr[1];
        #pragma unroll
        for (int i = 0; i < 4; i++) {
            float4 q = (i == 0) ? r0 : (i == 1) ? r1 : (i == 2) ? r2 : r3;
            int c = (q.x == T) + (q.y == T) + (q.z == T) + (q.w == T);
            int incl = warp_incl_scan(c, lane);
            if (lane == 31) s_warp[wid] = incl;
            __syncthreads();
            if (wid == 0) {
                int w = (lane < 8) ? s_warp[lane] : 0;
                int wi = warp_incl_scan(w, lane);
                if (lane < 8) s_warp[lane] = wi;
            }
            __syncthreads();
            int offset = wid ? s_warp[wid - 1] : 0;
            int b = chunkbase + offset + incl - c;
            if (i == 0) base0 = b; else if (i == 1) base1 = b;
            else if (i == 2) base2 = b; else base3 = b;
            chunkbase += s_warp[7];
            __syncthreads();
        }
        (void)rr;
    }

    const float gain = s_gain;

    // ---- write pass: from registers (no 2nd global read) ----
    #pragma unroll
    for (int i = 0; i < 4; i++) {
        float4 q = (i == 0) ? r0 : (i == 1) ? r1 : (i == 2) ? r2 : r3;
        int rr_ = (i == 0) ? base0 : (i == 1) ? base1 : (i == 2) ? base2 : base3;
        float o[4];
        float in[4] = { q.x, q.y, q.z, q.w };
        #pragma unroll
        for (int j = 0; j < 4; j++) {
            float v = in[j];
            bool inc;
            if (!use_rank) {
                inc = (v >= T);
            } else {
                if (v > T) inc = true;
                else if (v == T) { inc = (rr_ < needed); rr_++; }
                else inc = false;
            }
            o[j] = inc ? (v * gain) : 0.0f;
        }
        orow[tid + i * NT] = make_float4(o[0], o[1], o[2], o[3]);
    }
}

extern "C" void kernel_launch(void* const* d_in, const int* in_sizes, int n_in,
                              void* d_out, int out_size) {
    const float* x = (const float*)d_in[0];
    float* out = (float*)d_out;
    int nrows = in_sizes[0] / DCOLS;
    diff_gated_topk_kernel<<<nrows, NT>>>(x, out);
}

// round 5
// speedup vs baseline: 17.8668x; 1.2290x over previous
#include <cuda_runtime.h>
#include <cstdint>
#include <float.h>

// DiffGatedTopK: x [N=16384, D=4096] fp32.
// k = int(D*0.15) = 614. out = x * topk_mask * (sigmoid(top1-top2)*3 + 1)

#define DCOLS 4096
#define KSEL  614
#define NT    256
#define GAIN_C 3.0f
#define CAP   48

// float <-> order-preserving unsigned key (interval bookkeeping + top-2 reduce)
__device__ __forceinline__ unsigned f2k_f(float f) {
    unsigned u = __float_as_uint(f);
    return u ^ ((unsigned)(((int)u) >> 31) | 0x80000000u);
}
__device__ __forceinline__ float k2f(unsigned k) {
    unsigned b = (k & 0x80000000u) ? (k ^ 0x80000000u) : ~k;
    return __uint_as_float(b);
}

__device__ __forceinline__ int warp_incl_scan(int v, int lane) {
    #pragma unroll
    for (int o = 1; o < 32; o <<= 1) {
        int n = __shfl_up_sync(0xFFFFFFFFu, v, o);
        if (lane >= o) v += n;
    }
    return v;
}

// count of the 16 register-resident values >= t
#define CNT16_GE(t, res) do {                                            \
    int _c = 0;                                                          \
    _c += (r0.x >= (t)) + (r0.y >= (t)) + (r0.z >= (t)) + (r0.w >= (t));\
    _c += (r1.x >= (t)) + (r1.y >= (t)) + (r1.z >= (t)) + (r1.w >= (t));\
    _c += (r2.x >= (t)) + (r2.y >= (t)) + (r2.z >= (t)) + (r2.w >= (t));\
    _c += (r3.x >= (t)) + (r3.y >= (t)) + (r3.z >= (t)) + (r3.w >= (t));\
    (res) = _c; } while (0)

__global__ void __launch_bounds__(NT, 6)
diff_gated_topk_kernel(const float* __restrict__ x, float* __restrict__ out) {
    const int tid  = threadIdx.x;
    const int lane = tid & 31;
    const int wid  = tid >> 5;

    const float4* __restrict__ xr =
        reinterpret_cast<const float4*>(x + (size_t)blockIdx.x * DCOLS);
    float4* __restrict__ orow =
        reinterpret_cast<float4*>(out + (size_t)blockIdx.x * DCOLS);

    __shared__ int      s_cnt[2][8];   // double-buffered per-warp count partials
    __shared__ unsigned s_m[16];       // per-warp (M1,M2) keys for top-2
    __shared__ float    s_gain;
    __shared__ int      s_warp[8];     // scan scratch (rare tie path)
    __shared__ float    s_small[CAP];  // epilogue candidate buffer
    __shared__ int      s_n;
    __shared__ float    s_T;
    __shared__ int      s_needed, s_eqc;

    // ---- load 16 values/thread, coalesced float4; track top-2 locally ----
    float4 r0, r1, r2, r3;
    float m1 = -FLT_MAX, m2 = -FLT_MAX;
    r0 = xr[tid];            r1 = xr[tid + NT];
    r2 = xr[tid + 2 * NT];   r3 = xr[tid + 3 * NT];
    #define T2(v) { float _v = (v); if (_v > m1) { m2 = m1; m1 = _v; } else if (_v > m2) m2 = _v; }
    T2(r0.x) T2(r0.y) T2(r0.z) T2(r0.w)
    T2(r1.x) T2(r1.y) T2(r1.z) T2(r1.w)
    T2(r2.x) T2(r2.y) T2(r2.z) T2(r2.w)
    T2(r3.x) T2(r3.y) T2(r3.z) T2(r3.w)
    #undef T2

    // ---- warp top-2 (multiset) via REDUX on keys ----
    {
        unsigned k1 = f2k_f(m1), k2v = f2k_f(m2);
        unsigned M1 = __reduce_max_sync(0xFFFFFFFFu, k1);
        unsigned bal = __ballot_sync(0xFFFFFFFFu, k1 == M1);
        int leader = __ffs(bal) - 1;
        unsigned cand = (lane == leader) ? k2v : k1;
        unsigned M2 = __reduce_max_sync(0xFFFFFFFFu, cand);
        if (lane == 0) { s_m[2 * wid] = M1; s_m[2 * wid + 1] = M2; }
    }
    if (tid == 0) s_n = 0;
    __syncthreads();
    if (tid == 0) {
        unsigned a1 = s_m[0], a2 = s_m[1];
        #pragma unroll
        for (int w = 1; w < 8; w++) {
            unsigned b1 = s_m[2 * w], b2 = s_m[2 * w + 1];
            unsigned n1 = max(a1, b1);
            a2 = max(min(a1, b1), max(a2, b2));
            a1 = n1;
        }
        float d = k2f(a1) - k2f(a2);   // >= 0
        s_gain = GAIN_C / (1.0f + expf(-d)) + 1.0f;
    }

    // ---- bracket round: two probes counted in one pass (packed 16-bit) ----
    const float PA = 0.95f, PB = 1.13f;   // threshold ~= 1.036 +- 0.024
    int cA, cB;
    CNT16_GE(PA, cA);
    CNT16_GE(PB, cB);
    {
        int pc = cA | (cB << 16);
        pc = __reduce_add_sync(0xFFFFFFFFu, pc);
        if (lane == 0) s_cnt[0][wid] = pc;
        __syncthreads();
        int v = (lane < 8) ? s_cnt[0][lane] : 0;
        v += __shfl_down_sync(0xFFFFFFFFu, v, 4);
        v += __shfl_down_sync(0xFFFFFFFFu, v, 2);
        v += __shfl_down_sync(0xFFFFFFFFu, v, 1);
        v = __shfl_sync(0xFFFFFFFFu, v, 0);
        cA = v & 0xFFFF; cB = v >> 16;
    }

    unsigned lo, hi; int clo, chi;
    if (cA >= KSEL && cB < KSEL)      { lo = f2k_f(PA); clo = cA;   hi = f2k_f(PB); chi = cB; }
    else if (cB >= KSEL)              { lo = f2k_f(PB); clo = cB;   hi = f2k_f(FLT_MAX); chi = 0; }
    else                              { lo = f2k_f(-FLT_MAX); clo = DCOLS; hi = f2k_f(PA); chi = cA; }

    // ---- interpolation / bisection descent ----
    int active = clo - chi;
    int parity = 1, round = 0;
    while (active > CAP && hi - lo > 1u && round < 64) {
        unsigned m;
        if (round & 1) {
            m = lo + ((hi - lo) >> 1);
        } else {
            float flo = k2f(lo), fhi = k2f(hi);
            float t = flo + (fhi - flo) * ((float)(clo - KSEL) / (float)(clo - chi));
            m = f2k_f(t);
            if (m <= lo || m >= hi) m = lo + ((hi - lo) >> 1);
        }
        float fm = k2f(m);
        int cm;
        CNT16_GE(fm, cm);
        cm = __reduce_add_sync(0xFFFFFFFFu, cm);
        if (lane == 0) s_cnt[parity][wid] = cm;
        __syncthreads();
        int v = (lane < 8) ? s_cnt[parity][lane] : 0;
        v += __shfl_down_sync(0xFFFFFFFFu, v, 4);
        v += __shfl_down_sync(0xFFFFFFFFu, v, 2);
        v += __shfl_down_sync(0xFFFFFFFFu, v, 1);
        cm = __shfl_sync(0xFFFFFFFFu, v, 0);
        parity ^= 1;
        if (cm >= KSEL) { lo = m; clo = cm; } else { hi = m; chi = cm; }
        active = clo - chi;
        round++;
    }

    float T; int needed, eqc;
    if (active <= CAP) {
        // ---- epilogue: compact candidates in [flo, fhi), rank exactly ----
        const float flo = k2f(lo), fhi = k2f(hi);
        __syncthreads();                 // s_n==0 visible; prior s_cnt reads done
        #define PUT(v) { float _v = (v); if (_v >= flo && _v < fhi) { \
                           int _p = atomicAdd(&s_n, 1); if (_p < CAP) s_small[_p] = _v; } }
        PUT(r0.x) PUT(r0.y) PUT(r0.z) PUT(r0.w)
        PUT(r1.x) PUT(r1.y) PUT(r1.z) PUT(r1.w)
        PUT(r2.x) PUT(r2.y) PUT(r2.z) PUT(r2.w)
        PUT(r3.x) PUT(r3.y) PUT(r3.z) PUT(r3.w)
        #undef PUT
        __syncthreads();
        int cnt = min(s_n, CAP);         // == active
        int k_small = KSEL - chi;        // 1 <= k_small <= cnt
        if (tid < cnt) {
            float v = s_small[tid];
            int cge = 0, cgt = 0;
            for (int j = 0; j < cnt; j++) {
                float w = s_small[j];
                cge += (w >= v);
                cgt += (w > v);
            }
            if (cgt < k_small && k_small <= cge) {   // v is the k_small-th largest
                s_T = v;
                s_needed = k_small - cgt;            // how many ==T to include
                s_eqc = cge - cgt;                   // total ==T in row
            }
        }
        __syncthreads();
        T = s_T; needed = s_needed; eqc = s_eqc;
    } else {
        // interval width 1: all active values equal k2f(lo)
        T = k2f(lo); needed = KSEL - chi; eqc = active;
        __syncthreads();                 // keep s_gain ordering uniform
    }

    const bool use_rank = (needed != eqc);   // rare: partial tie at threshold

    // ---- rare path: rank ==T elements in exact column order ----
    // column(c) = i*1024 + tid*4 + j  -> order over (i, tid, j)
    int base0 = 0, base1 = 0, base2 = 0, base3 = 0;
    if (use_rank) {
        int chunkbase = 0;
        #pragma unroll
        for (int i = 0; i < 4; i++) {
            float4 q = (i == 0) ? r0 : (i == 1) ? r1 : (i == 2) ? r2 : r3;
            int c = (q.x == T) + (q.y == T) + (q.z == T) + (q.w == T);
            int incl = warp_incl_scan(c, lane);
            if (lane == 31) s_warp[wid] = incl;
            __syncthreads();
            if (wid == 0) {
                int w = (lane < 8) ? s_warp[lane] : 0;
                int wi = warp_incl_scan(w, lane);
                if (lane < 8) s_warp[lane] = wi;
            }
            __syncthreads();
            int offset = wid ? s_warp[wid - 1] : 0;
            int b = chunkbase + offset + incl - c;
            if (i == 0) base0 = b; else if (i == 1) base1 = b;
            else if (i == 2) base2 = b; else base3 = b;
            chunkbase += s_warp[7];
            __syncthreads();
        }
    }

    const float gain = s_gain;

    // ---- write pass: from registers (no 2nd global read) ----
    #pragma unroll
    for (int i = 0; i < 4; i++) {
        float4 q = (i == 0) ? r0 : (i == 1) ? r1 : (i == 2) ? r2 : r3;
        int rr_ = (i == 0) ? base0 : (i == 1) ? base1 : (i == 2) ? base2 : base3;
        float in[4] = { q.x, q.y, q.z, q.w };
        float o[4];
        #pragma unroll
        for (int j = 0; j < 4; j++) {
            float v = in[j];
            bool inc;
            if (!use_rank) {
                inc = (v >= T);
            } else {
                if (v > T) inc = true;
                else if (v == T) { inc = (rr_ < needed); rr_++; }
                else inc = false;
            }
            o[j] = inc ? (v * gain) : 0.0f;
        }
        orow[tid + i * NT] = make_float4(o[0], o[1], o[2], o[3]);
    }
}

extern "C" void kernel_launch(void* const* d_in, const int* in_sizes, int n_in,
                              void* d_out, int out_size) {
    const float* x = (const float*)d_in[0];
    float* out = (float*)d_out;
    int nrows = in_sizes[0] / DCOLS;
    diff_gated_topk_kernel<<<nrows, NT>>>(x, out);
}

// round 7
// speedup vs baseline: 19.6012x; 1.0971x over previous
#include <cuda_runtime.h>
#include <cstdint>
#include <float.h>

// DiffGatedTopK: x [N=16384, D=4096] fp32.
// k = int(D*0.15) = 614. out = x * topk_mask * (sigmoid(top1-top2)*3 + 1)

#define DCOLS 4096
#define KSEL  614
#define NT    256
#define GAIN_C 3.0f
#define CAP   32

// float <-> order-preserving unsigned key (fallback / top-2 reduce only)
__device__ __forceinline__ unsigned f2k_f(float f) {
    unsigned u = __float_as_uint(f);
    return u ^ ((unsigned)(((int)u) >> 31) | 0x80000000u);
}
__device__ __forceinline__ float k2f(unsigned k) {
    unsigned b = (k & 0x80000000u) ? (k ^ 0x80000000u) : ~k;
    return __uint_as_float(b);
}

__device__ __forceinline__ int warp_incl_scan(int v, int lane) {
    #pragma unroll
    for (int o = 1; o < 32; o <<= 1) {
        int n = __shfl_up_sync(0xFFFFFFFFu, v, o);
        if (lane >= o) v += n;
    }
    return v;
}

// count of the 16 register-resident values >= t
#define CNT16_GE(t, res) do {                                            \
    int _c = 0;                                                          \
    _c += (r0.x >= (t)) + (r0.y >= (t)) + (r0.z >= (t)) + (r0.w >= (t));\
    _c += (r1.x >= (t)) + (r1.y >= (t)) + (r1.z >= (t)) + (r1.w >= (t));\
    _c += (r2.x >= (t)) + (r2.y >= (t)) + (r2.z >= (t)) + (r2.w >= (t));\
    _c += (r3.x >= (t)) + (r3.y >= (t)) + (r3.z >= (t)) + (r3.w >= (t));\
    (res) = _c; } while (0)

__global__ void __launch_bounds__(NT, 6)
diff_gated_topk_kernel(const float* __restrict__ x, float* __restrict__ out) {
    const int tid  = threadIdx.x;
    const int lane = tid & 31;
    const int wid  = tid >> 5;

    const float4* __restrict__ xr =
        reinterpret_cast<const float4*>(x + (size_t)blockIdx.x * DCOLS);
    float4* __restrict__ orow =
        reinterpret_cast<float4*>(out + (size_t)blockIdx.x * DCOLS);

    __shared__ int      s_cnt[2][8];   // double-buffered per-warp count partials
    __shared__ unsigned s_m[16];       // per-warp (M1,M2) keys for top-2
    __shared__ float    s_gain;
    __shared__ int      s_warp[8];     // scan scratch (rare tie path)
    __shared__ float    s_small[CAP];  // epilogue candidate buffer
    __shared__ int      s_n;
    __shared__ float    s_T;
    __shared__ int      s_needed, s_eqc;

    // ---- load 16 values/thread, coalesced float4; track top-2 locally ----
    float4 r0, r1, r2, r3;
    float m1 = -FLT_MAX, m2 = -FLT_MAX;
    r0 = xr[tid];            r1 = xr[tid + NT];
    r2 = xr[tid + 2 * NT];   r3 = xr[tid + 3 * NT];
    #define T2(v) { float _v = (v); if (_v > m1) { m2 = m1; m1 = _v; } else if (_v > m2) m2 = _v; }
    T2(r0.x) T2(r0.y) T2(r0.z) T2(r0.w)
    T2(r1.x) T2(r1.y) T2(r1.z) T2(r1.w)
    T2(r2.x) T2(r2.y) T2(r2.z) T2(r2.w)
    T2(r3.x) T2(r3.y) T2(r3.z) T2(r3.w)
    #undef T2

    // ---- warp top-2 (multiset) via REDUX on keys ----
    {
        unsigned k1 = f2k_f(m1), k2v = f2k_f(m2);
        unsigned M1 = __reduce_max_sync(0xFFFFFFFFu, k1);
        unsigned bal = __ballot_sync(0xFFFFFFFFu, k1 == M1);
        int leader = __ffs(bal) - 1;
        unsigned cand = (lane == leader) ? k2v : k1;
        unsigned M2 = __reduce_max_sync(0xFFFFFFFFu, cand);
        if (lane == 0) { s_m[2 * wid] = M1; s_m[2 * wid + 1] = M2; }
    }

    // ---- bracket: two probes, packed 16-bit, same barrier as top-2 ----
    const float PA = 0.95f, PB = 1.13f;   // threshold ~= 1.036 +- 0.024
    int cA, cB;
    CNT16_GE(PA, cA);
    CNT16_GE(PB, cB);
    {
        int pc = cA | (cB << 16);
        pc = __reduce_add_sync(0xFFFFFFFFu, pc);
        if (lane == 0) s_cnt[0][wid] = pc;
    }
    if (tid == 0) s_n = 0;
    __syncthreads();
    {
        int v = (lane < 8) ? s_cnt[0][lane] : 0;
        v += __shfl_down_sync(0xFFFFFFFFu, v, 4);
        v += __shfl_down_sync(0xFFFFFFFFu, v, 2);
        v += __shfl_down_sync(0xFFFFFFFFu, v, 1);
        v = __shfl_sync(0xFFFFFFFFu, v, 0);
        cA = v & 0xFFFF; cB = v >> 16;
    }
    if (tid == 0) {
        unsigned a1 = s_m[0], a2 = s_m[1];
        #pragma unroll
        for (int w = 1; w < 8; w++) {
            unsigned b1 = s_m[2 * w], b2 = s_m[2 * w + 1];
            unsigned n1 = max(a1, b1);
            a2 = max(min(a1, b1), max(a2, b2));
            a1 = n1;
        }
        float d = k2f(a1) - k2f(a2);   // >= 0
        s_gain = GAIN_C / (1.0f + __expf(-d)) + 1.0f;
    }
    // s_gain read only after >=1 further barrier on every path.

    float lo, hi; int clo, chi;
    if (cA >= KSEL && cB < KSEL)      { lo = PA;       clo = cA;    hi = PB;      chi = cB; }
    else if (cB >= KSEL)              { lo = PB;       clo = cB;    hi = FLT_MAX; chi = 0;  }
    else                              { lo = -FLT_MAX; clo = DCOLS; hi = PA;      chi = cA; }

    int active = clo - chi;
    int parity = 1;
    bool resolved = false;
    float T = 0.0f; int needed = 0, eqc = 0;

    // ---- straight-line interpolation rounds (common path: 1, sometimes 2) ----
    #pragma unroll
    for (int rr = 0; rr < 2; rr++) {
        if (active > CAP && !resolved) {           // block-uniform
            float fm = lo + (hi - lo) * ((float)(clo - KSEL) / (float)(clo - chi));
            if (!(fm > lo && fm < hi)) fm = 0.5f * (lo + hi);
            if (fm > lo && fm < hi) {
                int cm;
                CNT16_GE(fm, cm);
                cm = __reduce_add_sync(0xFFFFFFFFu, cm);
                if (lane == 0) s_cnt[parity][wid] = cm;
                __syncthreads();
                int v = (lane < 8) ? s_cnt[parity][lane] : 0;
                v += __shfl_down_sync(0xFFFFFFFFu, v, 4);
                v += __shfl_down_sync(0xFFFFFFFFu, v, 2);
                v += __shfl_down_sync(0xFFFFFFFFu, v, 1);
                cm = __shfl_sync(0xFFFFFFFFu, v, 0);
                parity ^= 1;
                if (cm >= KSEL) { lo = fm; clo = cm; } else { hi = fm; chi = cm; }
                active = clo - chi;
            } else {
                // interval degenerate (<=1 ulp): all window values equal lo
                resolved = true; T = lo; needed = KSEL - chi; eqc = active;
                __syncthreads();       // s_gain visibility on this path
            }
        }
    }

    // ---- rare fallback: exact uint-space descent ----
    if (active > CAP && !resolved) {
        unsigned ulo = f2k_f(lo), uhi = f2k_f(hi);
        int round = 0;
        while (active > CAP && uhi - ulo > 1u) {
            unsigned um;
            if (round & 1) {
                um = ulo + ((uhi - ulo) >> 1);
            } else {
                float t = lo + (hi - lo) * ((float)(clo - KSEL) / (float)(clo - chi));
                um = f2k_f(t);
                if (um <= ulo || um >= uhi) um = ulo + ((uhi - ulo) >> 1);
            }
            float fm = k2f(um);
            int cm;
            CNT16_GE(fm, cm);
            cm = __reduce_add_sync(0xFFFFFFFFu, cm);
            if (lane == 0) s_cnt[parity][wid] = cm;
            __syncthreads();
            int v = (lane < 8) ? s_cnt[parity][lane] : 0;
            v += __shfl_down_sync(0xFFFFFFFFu, v, 4);
            v += __shfl_down_sync(0xFFFFFFFFu, v, 2);
            v += __shfl_down_sync(0xFFFFFFFFu, v, 1);
            cm = __shfl_sync(0xFFFFFFFFu, v, 0);
            parity ^= 1;
            if (cm >= KSEL) { ulo = um; lo = fm; clo = cm; }
            else            { uhi = um; hi = fm; chi = cm; }
            active = clo - chi;
            round++;
        }
        if (active > CAP) {     // width-1 interval: all equal
            resolved = true; T = k2f(ulo); needed = KSEL - chi; eqc = active;
        }
    }

    if (!resolved) {
        // ---- epilogue: compact <=32 candidates in [lo,hi), rank on warp 0 ----
        #define PUT(v) { float _v = (v); if (_v >= lo && _v < hi) { \
                           int _p = atomicAdd(&s_n, 1); if (_p < CAP) s_small[_p] = _v; } }
        PUT(r0.x) PUT(r0.y) PUT(r0.z) PUT(r0.w)
        PUT(r1.x) PUT(r1.y) PUT(r1.z) PUT(r1.w)
        PUT(r2.x) PUT(r2.y) PUT(r2.z) PUT(r2.w)
        PUT(r3.x) PUT(r3.y) PUT(r3.z) PUT(r3.w)
        #undef PUT
        __syncthreads();
        if (wid == 0) {
            const int cnt = min(s_n, CAP);        // == active
            const int k_small = KSEL - chi;       // 1 <= k_small <= cnt
            float v = (lane < cnt) ? s_small[lane] : -FLT_MAX;
            int cgt = 0, cge = 0;
            #pragma unroll
            for (int j = 0; j < CAP; j++) {
                float w = __shfl_sync(0xFFFFFFFFu, v, j);
                bool valid = (j < cnt);
                cgt += valid && (w > v);
                cge += valid && (w >= v);
            }
            if (lane < cnt && cgt < k_small && k_small <= cge) {
                s_T = v;
                s_needed = k_small - cgt;         // # of ==T to include
                s_eqc = cge - cgt;                // total ==T in row
            }
        }
        __syncthreads();
        T = s_T; needed = s_needed; eqc = s_eqc;
    } else {
        __syncthreads();        // uniform; s_gain visibility
    }

    const bool use_rank = (needed != eqc);   // rare: partial tie at threshold

    // ---- rare path: rank ==T elements in exact column order ----
    // column(c) = i*1024 + tid*4 + j  -> order over (i, tid, j)
    int base0 = 0, base1 = 0, base2 = 0, base3 = 0;
    if (use_rank) {
        int chunkbase = 0;
        #pragma unroll
        for (int i = 0; i < 4; i++) {
            float4 q = (i == 0) ? r0 : (i == 1) ? r1 : (i == 2) ? r2 : r3;
            int c = (q.x == T) + (q.y == T) + (q.z == T) + (q.w == T);
            int incl = warp_incl_scan(c, lane);
            if (lane == 31) s_warp[wid] = incl;
            __syncthreads();
            if (wid == 0) {
                int w = (lane < 8) ? s_warp[lane] : 0;
                int wi = warp_incl_scan(w, lane);
                if (lane < 8) s_warp[lane] = wi;
            }
            __syncthreads();
            int offset = wid ? s_warp[wid - 1] : 0;
            int b = chunkbase + offset + incl - c;
            if (i == 0) base0 = b; else if (i == 1) base1 = b;
            else if (i == 2) base2 = b; else base3 = b;
            chunkbase += s_warp[7];
            __syncthreads();
        }
    }

    const float gain = s_gain;

    // ---- write pass: from registers (no 2nd global read) ----
    #pragma unroll
    for (int i = 0; i < 4; i++) {
        float4 q = (i == 0) ? r0 : (i == 1) ? r1 : (i == 2) ? r2 : r3;
        int rr_ = (i == 0) ? base0 : (i == 1) ? base1 : (i == 2) ? base2 : base3;
        float in[4] = { q.x, q.y, q.z, q.w };
        float o[4];
        #pragma unroll
        for (int j = 0; j < 4; j++) {
            float v = in[j];
            bool inc;
            if (!use_rank) {
                inc = (v >= T);
            } else {
                if (v > T) inc = true;
                else if (v == T) { inc = (rr_ < needed); rr_++; }
                else inc = false;
            }
            o[j] = inc ? (v * gain) : 0.0f;
        }
        orow[tid + i * NT] = make_float4(o[0], o[1], o[2], o[3]);
    }
}

extern "C" void kernel_launch(void* const* d_in, const int* in_sizes, int n_in,
                              void* d_out, int out_size) {
    const float* x = (const float*)d_in[0];
    float* out = (float*)d_out;
    int nrows = in_sizes[0] / DCOLS;
    diff_gated_topk_kernel<<<nrows, NT>>>(x, out);
}